// round 3
// baseline (speedup 1.0000x reference)
#include <cuda_runtime.h>
#include <cstdint>

// Problem sizes (fixed by the reference)
#define B_N 8
#define L_N 4096
#define F_N 64

#define TILE_M 128
#define KC 32                    // k floats per chunk
#define NCHUNK (L_N / KC)        // 128
#define STAGES 4

// A stage: 128 rows x 36 floats (32 + 4 pad, keeps 16B alignment, kills bank conflicts)
#define A_ROW_F 36
#define A_STAGE_BYTES (TILE_M * A_ROW_F * 4)        // 18432
#define B_STAGE_BYTES (4 * 64 * 8 * 4)              // 8192
#define STAGE_BYTES (A_STAGE_BYTES + B_STAGE_BYTES) // 26624
#define OFF_BIAS (STAGES * STAGE_BYTES)             // 106496
#define SMEM_BYTES (OFF_BIAS + 256)                 // 106752

// hidden, pre-packed for mma.sync B fragments:
// element (b, l, o):  kb = l>>3, kr = l&7, p = (kr&3)*2 + (kr>>2)
// offset = ((b*512 + kb)*64 + o)*8 + p     (tf32-rounded values)
__device__ float g_hiddenB[(size_t)B_N * 512 * 64 * 8];

// ---------------------------------------------------------------------------
// helpers
// ---------------------------------------------------------------------------
__device__ __forceinline__ uint32_t smem_u32(const void* p) {
    uint32_t a;
    asm("{ .reg .u64 t; cvta.to.shared.u64 t, %1; cvt.u32.u64 %0, t; }" : "=r"(a) : "l"(p));
    return a;
}

__device__ __forceinline__ void cp16(uint32_t dst, const void* src) {
    asm volatile("cp.async.cg.shared.global [%0], [%1], 16;" :: "r"(dst), "l"(src) : "memory");
}

__device__ __forceinline__ void mma_tf32(float* c, uint32_t a0, uint32_t a1,
                                         uint32_t a2, uint32_t a3,
                                         uint32_t b0, uint32_t b1) {
    asm volatile(
        "mma.sync.aligned.m16n8k8.row.col.f32.tf32.tf32.f32 "
        "{%0,%1,%2,%3}, {%4,%5,%6,%7}, {%8,%9}, {%0,%1,%2,%3};"
        : "+f"(c[0]), "+f"(c[1]), "+f"(c[2]), "+f"(c[3])
        : "r"(a0), "r"(a1), "r"(a2), "r"(a3), "r"(b0), "r"(b1));
}

// ---------------------------------------------------------------------------
// Kernel A: hidden = text @ W, written tf32-rounded into packed-B layout
// ---------------------------------------------------------------------------
__global__ void __launch_bounds__(256) hidden_kernel(const float* __restrict__ text,
                                                     const float* __restrict__ weight) {
    __shared__ float s_text[64][65];
    __shared__ float s_w[64][64];
    const int b = blockIdx.y;
    const int l0 = blockIdx.x * 64;
    const int t = threadIdx.x;

    const float* tp = text + ((size_t)b * L_N + l0) * F_N;
#pragma unroll
    for (int j = 0; j < 16; j++) {
        int idx = j * 256 + t;  // 0..4095
        s_text[idx >> 6][idx & 63] = tp[idx];
        s_w[idx >> 6][idx & 63] = weight[idx];
    }
    __syncthreads();

    const int l = t & 63;
    const int og = t >> 6;  // 0..3 -> o = og*16 + i
    float acc[16];
#pragma unroll
    for (int i = 0; i < 16; i++) acc[i] = 0.0f;

    for (int f = 0; f < 64; f++) {
        float tv = s_text[l][f];
#pragma unroll
        for (int i = 0; i < 16; i++) acc[i] += tv * s_w[f][og * 16 + i];
    }

    const int lg = l0 + l;
    const int kb = lg >> 3;
    const int kr = lg & 7;
    const int p = (kr & 3) * 2 + (kr >> 2);
#pragma unroll
    for (int i = 0; i < 16; i++) {
        int o = og * 16 + i;
        uint32_t u;
        asm("cvt.rna.tf32.f32 %0, %1;" : "=r"(u) : "f"(acc[i]));
        g_hiddenB[(((size_t)b * 512 + kb) * 64 + o) * 8 + p] = __uint_as_float(u);
    }
}

// ---------------------------------------------------------------------------
// Kernel B: out[b] = adj[b] @ hidden[b] + bias
// 256 threads (8 warps), 128x64 CTA tile, each warp 16x64, mma.sync tf32.
// ---------------------------------------------------------------------------
__global__ void __launch_bounds__(256) gemm_kernel(const float* __restrict__ adj,
                                                   const float* __restrict__ bias,
                                                   float* __restrict__ out) {
    extern __shared__ char smem[];
    const uint32_t sb = smem_u32(smem);

    const int t = threadIdx.x;
    const int w = t >> 5;         // 0..7
    const int lane = t & 31;
    const int group = lane >> 2;  // 0..7
    const int tig = lane & 3;     // 0..3
    const int b = blockIdx.y;
    const int m0 = blockIdx.x * TILE_M;

    if (t < 64) *reinterpret_cast<float*>(smem + OFF_BIAS + t * 4) = bias[t];

    const float* aG = adj + ((size_t)b * L_N + m0) * L_N;
    const float* bG = g_hiddenB + (size_t)b * (512 * 64 * 8);

    // ---- cp.async stage issue (256 threads) ----
    auto issue = [&](int chunk, int slot) {
        uint32_t as = sb + slot * STAGE_BYTES;
        uint32_t bs = as + A_STAGE_BYTES;
        const float* aSrc = aG + chunk * KC;
#pragma unroll
        for (int j = 0; j < 4; j++) {
            int q = j * 256 + t;         // 0..1023
            int row = q >> 3, seg = q & 7;
            cp16(as + row * (A_ROW_F * 4) + seg * 16,
                 aSrc + (size_t)row * L_N + seg * 4);
        }
        const float* bSrc = bG + (size_t)chunk * 2048;  // 8KB contiguous
#pragma unroll
        for (int j = 0; j < 2; j++) {
            int q = j * 256 + t;         // 0..511
            cp16(bs + q * 16, bSrc + q * 4);
        }
    };

    float acc[8][4];
#pragma unroll
    for (int nt = 0; nt < 8; nt++)
#pragma unroll
        for (int r = 0; r < 4; r++) acc[nt][r] = 0.0f;

    issue(0, 0);
    asm volatile("cp.async.commit_group;" ::: "memory");
    issue(1, 1);
    asm volatile("cp.async.commit_group;" ::: "memory");
    issue(2, 2);
    asm volatile("cp.async.commit_group;" ::: "memory");

    for (int i = 0; i < NCHUNK; i++) {
        asm volatile("cp.async.wait_group 2;" ::: "memory");
        __syncthreads();

        if (i + 3 < NCHUNK) issue(i + 3, (i + 3) % STAGES);
        asm volatile("cp.async.commit_group;" ::: "memory");

        const char* as = smem + (i % STAGES) * STAGE_BYTES;
        const char* bs = as + A_STAGE_BYTES;

#pragma unroll
        for (int s = 0; s < 4; s++) {
            // B fragments: LDS.64, conflict-free (32 lanes -> 256B contiguous)
            uint32_t bf[8][2];
#pragma unroll
            for (int nt = 0; nt < 8; nt++) {
                float2 v = *reinterpret_cast<const float2*>(
                    bs + s * 2048 + (nt * 8 + group) * 32 + tig * 8);
                bf[nt][0] = __float_as_uint(v.x);
                bf[nt][1] = __float_as_uint(v.y);
            }
            // A fragments: rows w*16 + group (+8), cols s*8 + tig (+4)
            const int r0 = w * 16 + group;
            const char* ap = as + r0 * (A_ROW_F * 4) + (s * 8 + tig) * 4;
            uint32_t a0 = __float_as_uint(*reinterpret_cast<const float*>(ap));
            uint32_t a2 = __float_as_uint(*reinterpret_cast<const float*>(ap + 16));
            uint32_t a1 = __float_as_uint(
                *reinterpret_cast<const float*>(ap + 8 * (A_ROW_F * 4)));
            uint32_t a3 = __float_as_uint(
                *reinterpret_cast<const float*>(ap + 8 * (A_ROW_F * 4) + 16));
#pragma unroll
            for (int nt = 0; nt < 8; nt++)
                mma_tf32(acc[nt], a0, a1, a2, a3, bf[nt][0], bf[nt][1]);
        }
    }

    // ---- epilogue: + bias, direct STG ----
    const float* biasS = reinterpret_cast<const float*>(smem + OFF_BIAS);
    const int r0 = m0 + w * 16 + group;
    float* op0 = out + ((size_t)b * L_N + r0) * F_N;
    float* op1 = op0 + 8 * F_N;
#pragma unroll
    for (int nt = 0; nt < 8; nt++) {
        const int col = nt * 8 + tig * 2;
        const float b0 = biasS[col], b1 = biasS[col + 1];
        float2 v0 = make_float2(acc[nt][0] + b0, acc[nt][1] + b1);
        float2 v1 = make_float2(acc[nt][2] + b0, acc[nt][3] + b1);
        *reinterpret_cast<float2*>(op0 + col) = v0;
        *reinterpret_cast<float2*>(op1 + col) = v1;
    }
}

// ---------------------------------------------------------------------------
// launch
// ---------------------------------------------------------------------------
extern "C" void kernel_launch(void* const* d_in, const int* in_sizes, int n_in,
                              void* d_out, int out_size) {
    const float* text = (const float*)d_in[0];   // [8,4096,64]
    const float* adj = (const float*)d_in[1];    // [8,4096,4096]
    const float* weight = (const float*)d_in[2]; // [64,64]
    const float* bias = (const float*)d_in[3];   // [64]
    float* out = (float*)d_out;                  // [8,4096,64]

    cudaFuncSetAttribute(gemm_kernel, cudaFuncAttributeMaxDynamicSharedMemorySize,
                         SMEM_BYTES);

    hidden_kernel<<<dim3(L_N / 64, B_N), 256>>>(text, weight);
    gemm_kernel<<<dim3(L_N / TILE_M, B_N), 256, SMEM_BYTES>>>(adj, bias, out);
}

// round 5
// speedup vs baseline: 1.0698x; 1.0698x over previous
#include <cuda_runtime.h>
#include <cstdint>

// Problem sizes (fixed by the reference)
#define B_N 8
#define L_N 4096
#define F_N 64

#define TILE_M 256
#define KC 32                    // k floats per chunk
#define NCHUNK (L_N / KC)        // 128
#define STAGES 5

// A stage: 256 rows x 32 floats, XOR-swizzled 16B chunks (no padding needed)
#define A_STAGE_BYTES (TILE_M * KC * 4)             // 32768
#define B_STAGE_BYTES (4 * 64 * 8 * 4)              // 8192
#define STAGE_BYTES (A_STAGE_BYTES + B_STAGE_BYTES) // 40960
#define OFF_BIAS (STAGES * STAGE_BYTES)             // 204800
#define SMEM_BYTES (OFF_BIAS + 256)                 // 205056

// hidden, pre-packed for mma.sync B fragments:
// element (b, l, o):  kb = l>>3, kr = l&7, p = (kr&3)*2 + (kr>>2)
// offset = ((b*512 + kb)*64 + o)*8 + p     (tf32-rounded values)
__device__ float g_hiddenB[(size_t)B_N * 512 * 64 * 8];

// ---------------------------------------------------------------------------
// helpers
// ---------------------------------------------------------------------------
__device__ __forceinline__ uint32_t smem_u32(const void* p) {
    uint32_t a;
    asm("{ .reg .u64 t; cvta.to.shared.u64 t, %1; cvt.u32.u64 %0, t; }" : "=r"(a) : "l"(p));
    return a;
}

__device__ __forceinline__ void cp16(uint32_t dst, const void* src) {
    asm volatile("cp.async.cg.shared.global [%0], [%1], 16;" :: "r"(dst), "l"(src) : "memory");
}

__device__ __forceinline__ void mma_tf32(float* c, uint32_t a0, uint32_t a1,
                                         uint32_t a2, uint32_t a3,
                                         uint32_t b0, uint32_t b1) {
    asm volatile(
        "mma.sync.aligned.m16n8k8.row.col.f32.tf32.tf32.f32 "
        "{%0,%1,%2,%3}, {%4,%5,%6,%7}, {%8,%9}, {%0,%1,%2,%3};"
        : "+f"(c[0]), "+f"(c[1]), "+f"(c[2]), "+f"(c[3])
        : "r"(a0), "r"(a1), "r"(a2), "r"(a3), "r"(b0), "r"(b1));
}

// ---------------------------------------------------------------------------
// Kernel A: hidden = text @ W, written tf32-rounded into packed-B layout
// ---------------------------------------------------------------------------
__global__ void __launch_bounds__(256) hidden_kernel(const float* __restrict__ text,
                                                     const float* __restrict__ weight) {
    __shared__ float s_text[64][65];
    __shared__ float s_w[64][64];
    const int b = blockIdx.y;
    const int l0 = blockIdx.x * 64;
    const int t = threadIdx.x;

    const float* tp = text + ((size_t)b * L_N + l0) * F_N;
#pragma unroll
    for (int j = 0; j < 16; j++) {
        int idx = j * 256 + t;  // 0..4095
        s_text[idx >> 6][idx & 63] = tp[idx];
        s_w[idx >> 6][idx & 63] = weight[idx];
    }
    __syncthreads();

    const int l = t & 63;
    const int og = t >> 6;  // 0..3 -> o = og*16 + i
    float acc[16];
#pragma unroll
    for (int i = 0; i < 16; i++) acc[i] = 0.0f;

    for (int f = 0; f < 64; f++) {
        float tv = s_text[l][f];
#pragma unroll
        for (int i = 0; i < 16; i++) acc[i] += tv * s_w[f][og * 16 + i];
    }

    const int lg = l0 + l;
    const int kb = lg >> 3;
    const int kr = lg & 7;
    const int p = (kr & 3) * 2 + (kr >> 2);
#pragma unroll
    for (int i = 0; i < 16; i++) {
        int o = og * 16 + i;
        uint32_t u;
        asm("cvt.rna.tf32.f32 %0, %1;" : "=r"(u) : "f"(acc[i]));
        g_hiddenB[(((size_t)b * 512 + kb) * 64 + o) * 8 + p] = __uint_as_float(u);
    }
}

// ---------------------------------------------------------------------------
// Kernel B: out[b] = adj[b] @ hidden[b] + bias
// 256 threads (8 warps), 256x64 CTA tile, each warp 32x64 (mt=2), mma.sync tf32.
// A tile XOR-swizzled: 16B chunk index seg -> seg ^ (row & 7).
// ---------------------------------------------------------------------------
__global__ void __launch_bounds__(256) gemm_kernel(const float* __restrict__ adj,
                                                   const float* __restrict__ bias,
                                                   float* __restrict__ out) {
    extern __shared__ char smem[];
    const uint32_t sb = smem_u32(smem);

    const int t = threadIdx.x;
    const int w = t >> 5;         // 0..7
    const int lane = t & 31;
    const int group = lane >> 2;  // 0..7
    const int tig = lane & 3;     // 0..3
    const int b = blockIdx.y;
    const int m0 = blockIdx.x * TILE_M;

    if (t < 64) *reinterpret_cast<float*>(smem + OFF_BIAS + t * 4) = bias[t];

    const float* aG = adj + ((size_t)b * L_N + m0) * L_N;
    const float* bG = g_hiddenB + (size_t)b * (512 * 64 * 8);

    // ---- cp.async stage issue (256 threads) ----
    auto issue = [&](int chunk, int slot) {
        uint32_t as = sb + slot * STAGE_BYTES;
        uint32_t bs = as + A_STAGE_BYTES;
        const float* aSrc = aG + chunk * KC;
#pragma unroll
        for (int j = 0; j < 8; j++) {
            int q = j * 256 + t;         // 0..2047
            int row = q >> 3, seg = q & 7;
            cp16(as + row * 128 + ((seg ^ (row & 7)) << 4),
                 aSrc + (size_t)row * L_N + seg * 4);
        }
        const float* bSrc = bG + (size_t)chunk * 2048;  // 8KB contiguous
#pragma unroll
        for (int j = 0; j < 2; j++) {
            int q = j * 256 + t;         // 0..511
            cp16(bs + q * 16, bSrc + q * 4);
        }
    };

    float acc[2][8][4];
#pragma unroll
    for (int mt = 0; mt < 2; mt++)
#pragma unroll
        for (int nt = 0; nt < 8; nt++)
#pragma unroll
            for (int r = 0; r < 4; r++) acc[mt][nt][r] = 0.0f;

    issue(0, 0);
    asm volatile("cp.async.commit_group;" ::: "memory");
    issue(1, 1);
    asm volatile("cp.async.commit_group;" ::: "memory");
    issue(2, 2);
    asm volatile("cp.async.commit_group;" ::: "memory");
    issue(3, 3);
    asm volatile("cp.async.commit_group;" ::: "memory");

    for (int i = 0; i < NCHUNK; i++) {
        asm volatile("cp.async.wait_group 3;" ::: "memory");
        __syncthreads();

        if (i + 4 < NCHUNK) issue(i + 4, (i + 4) % STAGES);
        asm volatile("cp.async.commit_group;" ::: "memory");

        const char* as = smem + (i % STAGES) * STAGE_BYTES;
        const char* bs = as + A_STAGE_BYTES;

#pragma unroll
        for (int s = 0; s < 4; s++) {
            // B fragments: LDS.64, conflict-free (32 lanes -> 256B contiguous)
            uint32_t bf[8][2];
#pragma unroll
            for (int nt = 0; nt < 8; nt++) {
                float2 v = *reinterpret_cast<const float2*>(
                    bs + s * 2048 + (nt * 8 + group) * 32 + tig * 8);
                bf[nt][0] = __float_as_uint(v.x);
                bf[nt][1] = __float_as_uint(v.y);
            }
            // A fragments: swizzled chunks; rows r0, r0+8 share (row&7)==group
            const int c0 = ((2 * s) ^ group) << 4;      // chunk for cols 8s..8s+3
            const int c1 = ((2 * s + 1) ^ group) << 4;  // chunk for cols 8s+4..8s+7
#pragma unroll
            for (int mt = 0; mt < 2; mt++) {
                const int r0 = w * 32 + mt * 16 + group;
                const char* rp = as + r0 * 128;
                uint32_t a0 = __float_as_uint(
                    *reinterpret_cast<const float*>(rp + c0 + tig * 4));
                uint32_t a2 = __float_as_uint(
                    *reinterpret_cast<const float*>(rp + c1 + tig * 4));
                uint32_t a1 = __float_as_uint(
                    *reinterpret_cast<const float*>(rp + 8 * 128 + c0 + tig * 4));
                uint32_t a3 = __float_as_uint(
                    *reinterpret_cast<const float*>(rp + 8 * 128 + c1 + tig * 4));
#pragma unroll
                for (int nt = 0; nt < 8; nt++)
                    mma_tf32(acc[mt][nt], a0, a1, a2, a3, bf[nt][0], bf[nt][1]);
            }
        }
    }

    // ---- epilogue: + bias, direct STG ----
    const float* biasS = reinterpret_cast<const float*>(smem + OFF_BIAS);
#pragma unroll
    for (int mt = 0; mt < 2; mt++) {
        const int r0 = m0 + w * 32 + mt * 16 + group;
        float* op0 = out + ((size_t)b * L_N + r0) * F_N;
        float* op1 = op0 + 8 * F_N;
#pragma unroll
        for (int nt = 0; nt < 8; nt++) {
            const int col = nt * 8 + tig * 2;
            const float b0 = biasS[col], b1 = biasS[col + 1];
            float2 v0 = make_float2(acc[mt][nt][0] + b0, acc[mt][nt][1] + b1);
            float2 v1 = make_float2(acc[mt][nt][2] + b0, acc[mt][nt][3] + b1);
            *reinterpret_cast<float2*>(op0 + col) = v0;
            *reinterpret_cast<float2*>(op1 + col) = v1;
        }
    }
}

// ---------------------------------------------------------------------------
// launch
// ---------------------------------------------------------------------------
extern "C" void kernel_launch(void* const* d_in, const int* in_sizes, int n_in,
                              void* d_out, int out_size) {
    const float* text = (const float*)d_in[0];   // [8,4096,64]
    const float* adj = (const float*)d_in[1];    // [8,4096,4096]
    const float* weight = (const float*)d_in[2]; // [64,64]
    const float* bias = (const float*)d_in[3];   // [64]
    float* out = (float*)d_out;                  // [8,4096,64]

    cudaFuncSetAttribute(gemm_kernel, cudaFuncAttributeMaxDynamicSharedMemorySize,
                         SMEM_BYTES);

    hidden_kernel<<<dim3(L_N / 64, B_N), 256>>>(text, weight);
    gemm_kernel<<<dim3(L_N / TILE_M, B_N), 256, SMEM_BYTES>>>(adj, bias, out);
}